// round 16
// baseline (speedup 1.0000x reference)
#include <cuda_runtime.h>
#include <math.h>

#define Bv 32
#define Cv 1024
#define BC_TOTAL (Bv * Cv)      // 32768
#define HW 784                  // 28*28
#define NMASK 154               // 153 masks + 1 global-max term
#define CHB 64                  // channels per block
#define K1_BLOCKS (BC_TOTAL / CHB)   // 512
#define PITCH 60                // words/channel/tile (chunk stride 15 = 7 mod 8)
#define BUFW (CHB * PITCH)      // 3840 words = 15360 B per buffer
#define NBUF 3
#define NTILE 14                // two rows per tile
#define K1_SMEM (NBUF * BUFW * 4)    // 46080 B
// occupancy: smem -> 4/SM (184 KB), regs (64 via launch_bounds) -> 4/SM
// => 4 blocks/SM * 148 = 592 >= 512: ENTIRE GRID RESIDENT (spin-safe)

// ---- static device scratch (no allocations allowed) ----
__device__ float g_sqpart[NMASK * K1_BLOCKS]; // per-block partial squared sums
__device__ int   g_ctr = 0;                   // grid-barrier arrival counter
__device__ int   g_ctr2 = 0;                  // completion counter (resets both)

// ------------------------------------------------------------------
// Compile-time per-(quadrant, tile) GROUP lists. Tile t = contiguous
// rows {2t, 2t+1}; pixel pp = lr*28+col stored linearly at word pp.
// Entry = (4G) | c0<<12 | c1<<17 | c2<<22 | c3<<27; code: 0 skip,
// 1..19 ring rad, 30 corner (gm-only, first containing quadrant),
// 31 center (q0 only).
// Quadrants (ref order): q0 (dx>=0,dy>=0) q1 (dx<=0,dy>=0)
//                        q2 (dx>=0,dy<=0) q3 (dx<=0,dy<=0)
// ------------------------------------------------------------------
struct GLists { unsigned int e[4][NTILE][16]; int cnt[4][NTILE]; };
static constexpr GLists make_glists() {
    GLists L = {};
    for (int q = 0; q < 4; q++) for (int t = 0; t < NTILE; t++) L.cnt[q][t] = 0;
    for (int t = 0; t < NTILE; t++)
        for (int G = 0; G < 14; G++) {
            int codes[4][4] = {};
            bool any[4] = { false, false, false, false };
            for (int k = 0; k < 4; k++) {
                int pp = 4 * G + k;
                int lr = pp / 28, col = pp % 28;
                int i = 2 * t + lr;
                int dx = col - 14, dy = i - 14;
                int r2 = dx * dx + dy * dy;
                if (r2 == 0) { codes[0][k] = 31; any[0] = true; continue; }
                bool inq[4] = { dx >= 0 && dy >= 0, dx <= 0 && dy >= 0,
                                dx >= 0 && dy <= 0, dx <= 0 && dy <= 0 };
                if (r2 > 361) {
                    for (int q = 0; q < 4; q++)
                        if (inq[q]) { codes[q][k] = 30; any[q] = true; break; }
                } else {
                    int rad = 1; while (rad * rad < r2) rad++;
                    for (int q = 0; q < 4; q++)
                        if (inq[q]) { codes[q][k] = rad; any[q] = true; }
                }
            }
            for (int q = 0; q < 4; q++)
                if (any[q]) {
                    unsigned int e = (unsigned)(4 * G)
                        | ((unsigned)codes[q][0] << 12) | ((unsigned)codes[q][1] << 17)
                        | ((unsigned)codes[q][2] << 22) | ((unsigned)codes[q][3] << 27);
                    L.e[q][t][L.cnt[q][t]++] = e;
                }
        }
    return L;
}
static constexpr GLists GL = make_glists();

// ------------------------------------------------------------------
// cp.async helpers
// ------------------------------------------------------------------
__device__ __forceinline__ void cp_async16(unsigned int dst, const float4* src) {
    asm volatile("cp.async.cg.shared.global [%0], [%1], 16;" :: "r"(dst), "l"(src));
}
#define CP_COMMIT() asm volatile("cp.async.commit_group;" ::: "memory")
template<int N>
__device__ __forceinline__ void cp_wait() {
    asm volatile("cp.async.wait_group %0;" :: "n"(N) : "memory");
}

// ------------------------------------------------------------------
// Consume: fully unrolled; one LDS.128 per group (uniform broadcast),
// per-pixel codes fold to immediates; ring accumulators r[19] in regs.
// ------------------------------------------------------------------
template<int C>
__device__ __forceinline__ void procc(float v, float* r, float& gm0, float& cen) {
    if constexpr (C == 31) { cen = v; }
    else if constexpr (C == 30) { gm0 = fmaxf(gm0, v); }
    else if constexpr (C >= 1) { r[C - 1] = fmaxf(r[C - 1], v); }
}

template<int Q, int T, int K, int N>
struct Steps {
    __device__ __forceinline__ static void run(const float* sxc, float* r,
                                               float& gm0, float& cen) {
        constexpr unsigned e = GL.e[Q][T][K];
        float4 v = *(const float4*)(sxc + (e & 0xFFF));
        procc<((e >> 12) & 31)>(v.x, r, gm0, cen);
        procc<((e >> 17) & 31)>(v.y, r, gm0, cen);
        procc<((e >> 22) & 31)>(v.z, r, gm0, cen);
        procc<((e >> 27) & 31)>(v.w, r, gm0, cen);
        Steps<Q, T, K + 1, N>::run(sxc, r, gm0, cen);
    }
};
template<int Q, int T, int N>
struct Steps<Q, T, N, N> {
    __device__ __forceinline__ static void run(const float*, float*, float&, float&) {}
};

// Stage tile T (rows 2T,2T+1 contiguous = 224 B/channel) into buffer
// T%NBUF: 64 ch x 14 float4 = 896 coalesced 16 B cp.async copies.
template<int T>
__device__ __forceinline__ void stage_tile(const float4* __restrict__ gsrc,
                                           unsigned int sxa, int tid) {
    const unsigned int boff = (unsigned)((T % NBUF) * BUFW) * 4;
#pragma unroll
    for (int it = 0; it < 4; it++) {
        int m = tid + it * 256;
        if (it < 3 || tid < 128) {            // 896 copies total
            int ch = m / 14, f = m % 14;
            cp_async16(sxa + boff + (unsigned)(ch * PITCH + 4 * f) * 4,
                       gsrc + (size_t)ch * (HW / 4) + T * 14 + f);
        }
    }
    CP_COMMIT();
}

template<int T>
__device__ __forceinline__ void consume_dispatch(int q, const float* sxc, float* r,
                                                 float& gm0, float& cen) {
    if (q == 0)      Steps<0, T, 0, GL.cnt[0][T]>::run(sxc, r, gm0, cen);
    else if (q == 1) Steps<1, T, 0, GL.cnt[1][T]>::run(sxc, r, gm0, cen);
    else if (q == 2) Steps<2, T, 0, GL.cnt[2][T]>::run(sxc, r, gm0, cen);
    else             Steps<3, T, 0, GL.cnt[3][T]>::run(sxc, r, gm0, cen);
}

// Depth-1 pipeline, NBUF=3, ONE sync per tile. WAR safety: staging
// T+1 targets buffer (T+1)%3, last consumed at tile T-2; every
// warp's consume of T-2 is separated from this staging by the sync
// of tile T-1.
template<int T>
__device__ __forceinline__ void tiles(const float4* __restrict__ gsrc,
                                      unsigned int sxa, float* sx, int tid, int q,
                                      int ch, float* r, float& gm0, float& cen) {
    if constexpr (T + 1 < NTILE) {
        stage_tile<T + 1>(gsrc, sxa, tid);
        cp_wait<1>();
    } else {
        cp_wait<0>();
    }
    __syncthreads();
    consume_dispatch<T>(q, sx + (T % NBUF) * BUFW + ch * PITCH, r, gm0, cen);
    if constexpr (T + 1 < NTILE) tiles<T + 1>(gsrc, sxa, sx, tid, q, ch, r, gm0, cen);
}

// ------------------------------------------------------------------
// FUSED kernel: phase 1 streams x (ring maxes in regs, squared-norm
// partials -> g_sqpart); grid spin-barrier (whole grid resident);
// phase 2 rebuilds rn and finishes normalize-accumulate FROM
// REGISTERS. No intermediate state tensor at all.
// ------------------------------------------------------------------
__global__ __launch_bounds__(256, 4) void k_fused(const float* __restrict__ x,
                                                  float* __restrict__ out) {
    extern __shared__ __align__(16) float sx[];        // NBUF x 15360 B
    int tid = threadIdx.x;
    int q = tid >> 6;                 // 64-thread (2-warp) quadrant group
    int ch = tid & 63;
    int lane = tid & 31;
    int half = (tid >> 5) & 1;
    int blk = blockIdx.x;
    int bc0 = blk * CHB;

    unsigned int sxa = (unsigned int)__cvta_generic_to_shared(sx);
    const float4* gsrc = (const float4*)(x + (size_t)bc0 * HW);
    float r[19];
#pragma unroll
    for (int i = 0; i < 19; i++) r[i] = -INFINITY;
    float gm0 = -INFINITY, cen = 0.0f;

    stage_tile<0>(gsrc, sxa, tid);
    tiles<0>(gsrc, sxa, sx, tid, q, ch, r, gm0, cen);

    // ---- phase-1 epilogue: squared-norm partials only ----
    float* scen = sx;                 // [64]
    float* sgm = sx + 64;             // [4][64]
    float* spart = sx + 320;          // [NMASK][2]
    float* srn = sx + 640;            // [NMASK]   (phase 2)
    float* part = sx + 800;           // [4][64]   (phase 2)

    __syncthreads();                  // all consumes done; overlay safe
    if (q == 0) scen[ch] = cen;
    __syncthreads();
    float centerv = scen[ch];

    float gmq = fmaxf(gm0, centerv);
#pragma unroll
    for (int i = 0; i < 19; i++) gmq = fmaxf(gmq, r[i]);
    sgm[q * 64 + ch] = gmq;
    __syncthreads();
    float gmf = fmaxf(fmaxf(sgm[ch], sgm[64 + ch]),
                      fmaxf(sgm[128 + ch], sgm[192 + ch]));

#define WRED(m, val) { float _s = (val) * (val); \
    _s += __shfl_xor_sync(0xffffffffu, _s, 16); \
    _s += __shfl_xor_sync(0xffffffffu, _s, 8); \
    _s += __shfl_xor_sync(0xffffffffu, _s, 4); \
    _s += __shfl_xor_sync(0xffffffffu, _s, 2); \
    _s += __shfl_xor_sync(0xffffffffu, _s, 1); \
    if (lane == 0) spart[(m) * 2 + half] = _s; }

    if (q == 0) {
        WRED(0, fmaxf(centerv, 0.0f));
        WRED(153, gmf);
    }
    {
        float c = centerv;
#pragma unroll
        for (int rad = 1; rad <= 19; rad++) {
            float rv = r[rad - 1];
            c = fmaxf(c, rv);
            int mb = 1 + (rad - 1) * 8 + q * 2;
            WRED(mb, fmaxf(rv, 0.0f));
            WRED(mb + 1, fmaxf(c, 0.0f));
        }
    }
#undef WRED

    __syncthreads();
    if (tid < NMASK)
        g_sqpart[tid * K1_BLOCKS + blk] = spart[tid * 2] + spart[tid * 2 + 1];

    // ---- grid barrier (entire grid resident: 4 blocks/SM x 148) ----
    __syncthreads();
    if (tid == 0) {
        __threadfence();              // release g_sqpart writes
        atomicAdd(&g_ctr, 1);
        while (*((volatile int*)&g_ctr) < K1_BLOCKS) { __nanosleep(64); }
        __threadfence();              // acquire peers' g_sqpart writes
    }
    __syncthreads();

    // ---- phase 2a: rn for this batch (warp per mask, lanes 0..15) ----
    int b = blk / (K1_BLOCKS / Bv);   // = blk / 16
    int w8 = tid >> 5;
    for (int m = w8; m < NMASK; m += 8) {
        float s = (lane < 16)
            ? __ldcg(&g_sqpart[m * K1_BLOCKS + b * (K1_BLOCKS / Bv) + lane])
            : 0.0f;
#pragma unroll
        for (int o = 16; o; o >>= 1) s += __shfl_xor_sync(0xffffffffu, s, o);
        if (lane == 0) srn[m] = 1.0f / (sqrtf(s) + 1e-6f);
    }
    __syncthreads();

    // ---- phase 2b: normalize-accumulate from registers ----
    float c = centerv;
    float acc = 0.0f;
#pragma unroll
    for (int rad = 1; rad <= 19; rad++) {
        float rv = r[rad - 1];
        c = fmaxf(c, rv);
        int mb = 1 + (rad - 1) * 8 + q * 2;
        acc += fmaxf(rv, 0.0f) * srn[mb] + fmaxf(c, 0.0f) * srn[mb + 1];
    }
    if (q == 0)
        acc += fmaxf(centerv, 0.0f) * srn[0] + gmf * srn[153];
    part[q * 64 + ch] = acc;
    __syncthreads();
    if (tid < 64)
        out[bc0 + tid] = part[tid] + part[64 + tid] + part[128 + tid] + part[192 + tid];

    // ---- reset counters for next launch (all spinners have exited) ----
    if (tid == 0) {
        int o2 = atomicAdd(&g_ctr2, 1);
        if (o2 == K1_BLOCKS - 1) { g_ctr = 0; g_ctr2 = 0; }
    }
}

extern "C" void kernel_launch(void* const* d_in, const int* in_sizes, int n_in,
                              void* d_out, int out_size) {
    const float* x = (const float*)d_in[0];
    float* out = (float*)d_out;
    cudaFuncSetAttribute(k_fused, cudaFuncAttributeMaxDynamicSharedMemorySize, K1_SMEM);
    k_fused<<<K1_BLOCKS, 256, K1_SMEM>>>(x, out);
}

// round 17
// speedup vs baseline: 1.6888x; 1.6888x over previous
#include <cuda_runtime.h>
#include <math.h>

#define Bv 32
#define Cv 1024
#define BC_TOTAL (Bv * Cv)      // 32768
#define HW 784                  // 28*28
#define NMASK 154               // 153 masks + 1 global-max term
#define K1_BLOCKS 512           // 64 channels per block
#define SXPITCH 132             // words/channel (== 4 mod 32 -> conflict-free .128 phases)
#define BUFW (64 * SXPITCH)     // words per buffer
#define K1_SMEM (2 * BUFW * 4)  // 67584 B (double buffer)
#define NST 78                  // state floats per (b,c): center, gm, 76 rings

// ---- static device scratch (no allocations allowed) ----
__device__ float g_st[NST * BC_TOTAL];        // compact state, ~10.2 MB
__device__ float g_sqpart[K1_BLOCKS * NMASK]; // [block][mask] partial squared sums

// ------------------------------------------------------------------
// Compile-time per-(quadrant, tile) GROUP lists (round-10 layout).
// Tile t covers rows {2t,2t+1} (chunk 0) and {26-2t,27-2t} (chunk 1),
// stored LINEARLY: word = chunk*56 + lr*28 + col. Entry = word |
// c0<<12 | c1<<17 | c2<<22 | c3<<27; code: 0 skip, 1..19 ring rad,
// 30 corner (gm-only, first containing quadrant), 31 center (q0 only).
// Quadrants (ref order): q0 (dx>=0,dy>=0) q1 (dx<=0,dy>=0)
//                        q2 (dx>=0,dy<=0) q3 (dx<=0,dy<=0)
// ------------------------------------------------------------------
struct GLists { unsigned int e[4][7][16]; int cnt[4][7]; };
static constexpr GLists make_glists() {
    GLists L = {};
    for (int q = 0; q < 4; q++) for (int t = 0; t < 7; t++) L.cnt[q][t] = 0;
    for (int t = 0; t < 7; t++)
        for (int c2 = 0; c2 < 2; c2++)
            for (int G = 0; G < 14; G++) {
                int codes[4][4] = {};
                bool any[4] = { false, false, false, false };
                for (int k = 0; k < 4; k++) {
                    int pp = 4 * G + k;
                    int lr = pp / 28, col = pp % 28;
                    int i = (c2 == 0) ? (2 * t + lr) : (26 - 2 * t + lr);
                    int dx = col - 14, dy = i - 14;
                    int r2 = dx * dx + dy * dy;
                    if (r2 == 0) { codes[0][k] = 31; any[0] = true; continue; }
                    bool inq[4] = { dx >= 0 && dy >= 0, dx <= 0 && dy >= 0,
                                    dx >= 0 && dy <= 0, dx <= 0 && dy <= 0 };
                    if (r2 > 361) {
                        for (int q = 0; q < 4; q++)
                            if (inq[q]) { codes[q][k] = 30; any[q] = true; break; }
                    } else {
                        int rad = 1; while (rad * rad < r2) rad++;
                        for (int q = 0; q < 4; q++)
                            if (inq[q]) { codes[q][k] = rad; any[q] = true; }
                    }
                }
                int word = c2 * 56 + 4 * G;
                for (int q = 0; q < 4; q++)
                    if (any[q]) {
                        unsigned int e = (unsigned)word
                            | ((unsigned)codes[q][0] << 12) | ((unsigned)codes[q][1] << 17)
                            | ((unsigned)codes[q][2] << 22) | ((unsigned)codes[q][3] << 27);
                        L.e[q][t][L.cnt[q][t]++] = e;
                    }
            }
    return L;
}
static constexpr GLists GL = make_glists();

// ------------------------------------------------------------------
// cp.async helpers
// ------------------------------------------------------------------
__device__ __forceinline__ void cp_async16(unsigned int dst, const float4* src) {
    asm volatile("cp.async.cg.shared.global [%0], [%1], 16;" :: "r"(dst), "l"(src));
}
#define CP_COMMIT() asm volatile("cp.async.commit_group;" ::: "memory")
template<int N>
__device__ __forceinline__ void cp_wait() {
    asm volatile("cp.async.wait_group %0;" :: "n"(N) : "memory");
}

// ------------------------------------------------------------------
// Consume: fully unrolled; one LDS.128 per group (uniform broadcast),
// per-pixel codes fold to immediates; ring accumulators r[19] in regs.
// ------------------------------------------------------------------
template<int C>
__device__ __forceinline__ void procc(float v, float* r, float& gm0, float& cen) {
    if constexpr (C == 31) { cen = v; }
    else if constexpr (C == 30) { gm0 = fmaxf(gm0, v); }
    else if constexpr (C >= 1) { r[C - 1] = fmaxf(r[C - 1], v); }
}

template<int Q, int T, int K, int N>
struct Steps {
    __device__ __forceinline__ static void run(const float* sxc, float* r,
                                               float& gm0, float& cen) {
        constexpr unsigned e = GL.e[Q][T][K];
        float4 v = *(const float4*)(sxc + (e & 0xFFF));
        procc<((e >> 12) & 31)>(v.x, r, gm0, cen);
        procc<((e >> 17) & 31)>(v.y, r, gm0, cen);
        procc<((e >> 22) & 31)>(v.z, r, gm0, cen);
        procc<((e >> 27) & 31)>(v.w, r, gm0, cen);
        Steps<Q, T, K + 1, N>::run(sxc, r, gm0, cen);
    }
};
template<int Q, int T, int N>
struct Steps<Q, T, N, N> {
    __device__ __forceinline__ static void run(const float*, float*, float&, float&) {}
};

// Stage tile T into buffer T&1: coalesced 16 B copies, linear layout
// sx[ch*SXPITCH + chunk*56 + 4f].
template<int T>
__device__ __forceinline__ void stage_tile(const float4* __restrict__ gsrc,
                                           unsigned int sxa, int tid) {
    const unsigned int boff = (unsigned)((T & 1) * BUFW) * 4;
#pragma unroll
    for (int c2 = 0; c2 < 2; c2++) {
        const int base = (c2 == 0) ? (14 * T) : ((26 - 2 * T) * 7);
        const int w0 = c2 * 56;
#pragma unroll
        for (int it = 0; it < 4; it++) {
            int m = tid + it * 256;
            if (it < 3 || tid < 128) {
                int ch = m / 14, f = m % 14;
                cp_async16(sxa + boff + (unsigned)(ch * SXPITCH + w0 + 4 * f) * 4,
                           gsrc + (size_t)ch * (HW / 4) + base + f);
            }
        }
    }
    CP_COMMIT();
}

template<int T>
__device__ __forceinline__ void consume_dispatch(int q, const float* sxc, float* r,
                                                 float& gm0, float& cen) {
    if (q == 0)      Steps<0, T, 0, GL.cnt[0][T]>::run(sxc, r, gm0, cen);
    else if (q == 1) Steps<1, T, 0, GL.cnt[1][T]>::run(sxc, r, gm0, cen);
    else if (q == 2) Steps<2, T, 0, GL.cnt[2][T]>::run(sxc, r, gm0, cen);
    else             Steps<3, T, 0, GL.cnt[3][T]>::run(sxc, r, gm0, cen);
}

// Depth-1 double-buffered pipeline: stage T+1 before waiting on T.
template<int T>
__device__ __forceinline__ void tiles(const float4* __restrict__ gsrc,
                                      unsigned int sxa, float* sx, int tid, int q,
                                      int ch, float* r, float& gm0, float& cen) {
    if constexpr (T < 6) {
        stage_tile<T + 1>(gsrc, sxa, tid);
        cp_wait<1>();
    } else {
        cp_wait<0>();
    }
    __syncthreads();
    consume_dispatch<T>(q, sx + (T & 1) * BUFW + ch * SXPITCH, r, gm0, cen);
    __syncthreads();
    if constexpr (T < 6) tiles<T + 1>(gsrc, sxa, sx, tid, q, ch, r, gm0, cen);
}

// ------------------------------------------------------------------
// k1 (round-10 champion): block = 64 channels x 4 quadrant-threads
// (256). Double-buffered cp.async staging, LDS.128 broadcast consume,
// ring maxes in regs. Epilogue: center broadcast, quadrant gm
// combine, prefix maxes, coalesced state writes, inline squared-norm
// warp reductions -> g_sqpart in [block][mask] layout (coalesced).
// ------------------------------------------------------------------
__global__ __launch_bounds__(256) void k1_ringmax(const float* __restrict__ x) {
    extern __shared__ __align__(16) float sx[];        // 2 x 33792 B
    int tid = threadIdx.x;
    int q = tid >> 6;
    int ch = tid & 63;
    int lane = tid & 31;
    int half = (tid >> 5) & 1;
    int bc0 = blockIdx.x * 64;

    unsigned int sxa = (unsigned int)__cvta_generic_to_shared(sx);
    const float4* gsrc = (const float4*)(x + (size_t)bc0 * HW);
    float r[19];
#pragma unroll
    for (int i = 0; i < 19; i++) r[i] = -INFINITY;
    float gm0 = -INFINITY, cen = 0.0f;

    stage_tile<0>(gsrc, sxa, tid);
    tiles<0>(gsrc, sxa, sx, tid, q, ch, r, gm0, cen);

    // ---- epilogue (sx reused; last tiles<> ended with __syncthreads) ----
    float* scen = sx;                 // [64]
    float* sgm = sx + 64;             // [4][64]
    float* spart = sx + 64 + 256;     // [NMASK][2]

    if (q == 0) scen[ch] = cen;
    __syncthreads();
    float centerv = scen[ch];

    float gmq = fmaxf(gm0, centerv);
#pragma unroll
    for (int i = 0; i < 19; i++) gmq = fmaxf(gmq, r[i]);
    sgm[q * 64 + ch] = gmq;
    __syncthreads();

#define WRED(m, val) { float _s = (val) * (val); \
    _s += __shfl_xor_sync(0xffffffffu, _s, 16); \
    _s += __shfl_xor_sync(0xffffffffu, _s, 8); \
    _s += __shfl_xor_sync(0xffffffffu, _s, 4); \
    _s += __shfl_xor_sync(0xffffffffu, _s, 2); \
    _s += __shfl_xor_sync(0xffffffffu, _s, 1); \
    if (lane == 0) spart[(m) * 2 + half] = _s; }

    float* st = g_st + bc0 + ch;
    if (q == 0) {
        float gmf = fmaxf(fmaxf(sgm[ch], sgm[64 + ch]),
                          fmaxf(sgm[128 + ch], sgm[192 + ch]));
        st[0] = centerv;
        st[(size_t)BC_TOTAL] = gmf;
        WRED(0, fmaxf(centerv, 0.0f));
        WRED(153, gmf);
    }

    float c = centerv;
#pragma unroll
    for (int rad = 1; rad <= 19; rad++) {
        float rv = r[rad - 1];
        c = fmaxf(c, rv);
        st[(size_t)(2 + (rad - 1) * 4 + q) * BC_TOTAL] = rv;
        int mb = 1 + (rad - 1) * 8 + q * 2;
        WRED(mb, fmaxf(rv, 0.0f));
        WRED(mb + 1, fmaxf(c, 0.0f));
    }
#undef WRED

    __syncthreads();
    // [block][mask] layout: one coalesced 616 B burst per block
    if (tid < NMASK)
        g_sqpart[blockIdx.x * NMASK + tid] = spart[tid * 2] + spart[tid * 2 + 1];
}

// ------------------------------------------------------------------
// kf: inline rn + quadrant-split normalize-accumulate (k2_rn launch
// eliminated). Preamble: threads m<154 sum this batch's 16 block
// partials; each k-iteration reads 128 B contiguous per warp, 16
// independent loads -> full MLP. Then sub q reads only its own 19
// ring planes (coalesced), private prefix chain, accumulate.
// ------------------------------------------------------------------
__global__ __launch_bounds__(256) void kf_out(float* __restrict__ out) {
    __shared__ float rn[NMASK];
    __shared__ float part[4 * 64];
    int tid = threadIdx.x;
    int blk = blockIdx.x;                      // 512 blocks, 64 bc each
    int b = blk >> 4;
    if (tid < NMASK) {
        const float* p = g_sqpart + (size_t)(b * 16) * NMASK + tid;
        float s = 0.0f;
#pragma unroll
        for (int k = 0; k < 16; k++) s += __ldg(p + k * NMASK);
        rn[tid] = 1.0f / (sqrtf(s) + 1e-6f);
    }
    __syncthreads();

    int q = tid >> 6;
    int t = tid & 63;
    int bc = blk * 64 + t;
    const float* st = g_st + bc;

    float rv[19];
#pragma unroll
    for (int rad = 1; rad <= 19; rad++)
        rv[rad - 1] = __ldg(st + (size_t)(2 + (rad - 1) * 4 + q) * BC_TOTAL);

    float centerv = __ldg(st);
    float c = centerv;
    float acc = 0.0f;
#pragma unroll
    for (int rad = 1; rad <= 19; rad++) {
        float r = rv[rad - 1];
        c = fmaxf(c, r);
        int mb = 1 + (rad - 1) * 8 + q * 2;
        acc += fmaxf(r, 0.0f) * rn[mb] + fmaxf(c, 0.0f) * rn[mb + 1];
    }
    if (q == 0) {
        acc += fmaxf(centerv, 0.0f) * rn[0]
             + __ldg(st + (size_t)BC_TOTAL) * rn[153];
    }
    part[q * 64 + t] = acc;
    __syncthreads();
    if (tid < 64) {
        out[blk * 64 + tid] = part[tid] + part[64 + tid] + part[128 + tid] + part[192 + tid];
    }
}

extern "C" void kernel_launch(void* const* d_in, const int* in_sizes, int n_in,
                              void* d_out, int out_size) {
    const float* x = (const float*)d_in[0];
    float* out = (float*)d_out;
    cudaFuncSetAttribute(k1_ringmax, cudaFuncAttributeMaxDynamicSharedMemorySize, K1_SMEM);
    k1_ringmax<<<K1_BLOCKS, 256, K1_SMEM>>>(x);
    kf_out<<<K1_BLOCKS, 256>>>(out);
}